// round 17
// baseline (speedup 1.0000x reference)
#include <cuda_runtime.h>
#include <cuda_bf16.h>
#include <cstdint>

#define D       256
#define Kc      1024
#define NROWS   32768
#define Z_ELEMS 8388608
#define CAP     32
#define ASTRIDE 264          // bf16 row stride in smem (256 + 8 pad -> 528B rows)
#define RTILE   64           // rows per CTA
#define BTILE   64           // codes per B tile
#define NTILES  (Kc / BTILE) // 16
#define TILE_A  (RTILE * 528)   // 33792
#define TILE_Bb (BTILE * 528)   // 33792

// smem layout (fused kernel). Mainloop regions, then time-disjoint overlays:
//   OFF_A   [0,33792)      A bf16 tile   | overlay: z_s fp32 [64][257] (65792 <= 67584 spans A+B0)
//   OFF_B0  [33792,67584)  B stage 0     |   (part of z_s)
//   OFF_B1  [67584,101376) B stage 1     | overlay: tasks u32[2048] then q_s [32][257]
//   OFF_CN  [101376,105472) cn_s[1024]
//   OFF_MARG[105472,105728) marg_s[64]
//   OFF_RMIN[105728,105984) rmin_s[64]
//   OFF_CNT [105984,106240) cnt_s[64]
//   OFF_CAND[106240,110336) cand_s[64][CAP] u16 | overlay at end: rs[256] floats
//   OFF_ZN  [110336,110592) zn_s[64]
//   OFF_BEST[110592,111104) best_s[64] u64
//   OFF_CTRL[111104,111120) nq, ovf
#define OFF_A    0
#define OFF_B0   33792
#define OFF_B1   67584
#define OFF_CN   101376
#define OFF_MARG 105472
#define OFF_RMIN 105728
#define OFF_CNT  105984
#define OFF_CAND 106240
#define OFF_ZN   110336
#define OFF_BEST 110592
#define OFF_CTRL 111104
#define SMEM_TOT 111120

typedef unsigned int u32;
typedef unsigned long long u64;
typedef unsigned short u16;

// ---------------- device globals (no cudaMalloc allowed) -------------------
__device__ float g_cnorm[Kc];
__device__ int   g_cnmax;
__device__ float g_loss;
__device__ unsigned g_done;
__device__ uint4 g_cbbf4[Kc * 32];       // bf16(cb), [k][256] row-major (512B/row)

// ---------------- helpers --------------------------------------------------
__device__ __forceinline__ u32 smem_u32(const void* p) {
    u32 a; asm("{ .reg .u64 t; cvta.to.shared.u64 t, %1; cvt.u32.u64 %0, t; }" : "=r"(a) : "l"(p));
    return a;
}
__device__ __forceinline__ void ldsm4(u32* r, u32 addr) {
    asm volatile("ldmatrix.sync.aligned.m8n8.x4.shared.b16 {%0,%1,%2,%3}, [%4];"
        : "=r"(r[0]), "=r"(r[1]), "=r"(r[2]), "=r"(r[3]) : "r"(addr));
}
__device__ __forceinline__ void mma16816(float* c, const u32* a, u32 b0, u32 b1) {
    asm volatile("mma.sync.aligned.m16n8k16.row.col.f32.bf16.bf16.f32 "
        "{%0,%1,%2,%3}, {%4,%5,%6,%7}, {%8,%9}, {%0,%1,%2,%3};"
        : "+f"(c[0]), "+f"(c[1]), "+f"(c[2]), "+f"(c[3])
        : "r"(a[0]), "r"(a[1]), "r"(a[2]), "r"(a[3]), "r"(b0), "r"(b1));
}
__device__ __forceinline__ void cpasync16(u32 dst, const void* src) {
    asm volatile("cp.async.cg.shared.global [%0], [%1], 16;" :: "r"(dst), "l"(src));
}
__device__ __forceinline__ void cpcommit() {
    asm volatile("cp.async.commit_group;" ::: "memory");
}
__device__ __forceinline__ void cpwait0() {
    asm volatile("cp.async.wait_group 0;" ::: "memory");
}
__device__ __forceinline__ int f2ord(float f) {
    int i = __float_as_int(f);
    return i >= 0 ? i : i ^ 0x7FFFFFFF;
}
__device__ __forceinline__ float ord2f(int i) {
    return __int_as_float(i >= 0 ? i : i ^ 0x7FFFFFFF);
}
// unsigned monotone key for lexicographic (score, code) minimum
__device__ __forceinline__ u64 skey(float sc, int code) {
    u32 o = (u32)f2ord(sc) ^ 0x80000000u;
    return ((u64)o << 32) | (u32)code;
}

// ---------------------------------------------------------------------------
// k0: warp-per-code prep (validated ~7us). Coalesced row load + bf16 convert;
// lane 0 runs the bit-exact sequential unfused norm chain.
// ---------------------------------------------------------------------------
__global__ void __launch_bounds__(128)
prep_kernel(const float* __restrict__ cb) {
    __shared__ float stage[4][264];
    __shared__ float nrm[4];
    const int t    = threadIdx.x;
    const int lane = t & 31;
    const int w    = t >> 5;
    #pragma unroll
    for (int pass = 0; pass < 2; ++pass) {
        int c = blockIdx.x * 8 + pass * 4 + w;
        const float* row = cb + (size_t)c * D;
        float4 v0[2];
        u16 pk[8];
        #pragma unroll
        for (int h = 0; h < 2; ++h) {
            v0[h] = *(const float4*)&row[lane * 8 + h * 4];
            __nv_bfloat16 b0 = __float2bfloat16(v0[h].x);
            __nv_bfloat16 b1 = __float2bfloat16(v0[h].y);
            __nv_bfloat16 b2 = __float2bfloat16(v0[h].z);
            __nv_bfloat16 b3 = __float2bfloat16(v0[h].w);
            pk[h * 4 + 0] = *(u16*)&b0; pk[h * 4 + 1] = *(u16*)&b1;
            pk[h * 4 + 2] = *(u16*)&b2; pk[h * 4 + 3] = *(u16*)&b3;
            *(float4*)&stage[w][lane * 8 + h * 4] = v0[h];
        }
        g_cbbf4[(size_t)c * 32 + lane] = *(uint4*)pk;
        __syncwarp();
        if (lane == 0) {
            float s = 0.0f;
            #pragma unroll 8
            for (int d = 0; d < D; ++d) {
                float v = stage[w][d];
                s = __fadd_rn(s, __fmul_rn(v, v));   // sequential ascending d, unfused
            }
            g_cnorm[c] = s;
            nrm[w] = (pass == 0) ? s : fmaxf(nrm[w], s);
        }
        __syncwarp();
    }
    __syncthreads();
    if (t == 0)
        atomicMax(&g_cnmax, f2ord(fmaxf(fmaxf(nrm[0], nrm[1]), fmaxf(nrm[2], nrm[3]))));
}

// ---------------------------------------------------------------------------
// k1: FUSED mma + filter + exact verify + gather/STE/loss. One 64-row CTA
// does everything; candidates never leave smem. 2 CTAs/SM preserved.
// ---------------------------------------------------------------------------
__global__ void __launch_bounds__(256, 2)
fused_kernel(const float* __restrict__ z, const float* __restrict__ cb,
             float* __restrict__ out) {
    extern __shared__ char smr[];
    u16*   Asm    = (u16*)(smr + OFF_A);
    float* cn_s   = (float*)(smr + OFF_CN);
    float* marg_s = (float*)(smr + OFF_MARG);
    int*   rmin_s = (int*)(smr + OFF_RMIN);
    int*   cnt_s  = (int*)(smr + OFF_CNT);
    u16*   cand_s = (u16*)(smr + OFF_CAND);
    float* zn_s   = (float*)(smr + OFF_ZN);
    u64*   best_s = (u64*)(smr + OFF_BEST);
    int*   nq_p   = (int*)(smr + OFF_CTRL);
    int*   ovf_p  = (int*)(smr + OFF_CTRL + 4);
    // time-disjoint overlays
    float* z_s    = (float*)(smr + OFF_A);      // [64][257] after mainloop
    u32*   tasks  = (u32*)(smr + OFF_B1);       // verify phase
    float* q_s    = (float*)(smr + OFF_B1);     // [32][257] STE phase
    float* rs     = (float*)(smr + OFF_CAND);   // final reduce

    const int t      = threadIdx.x;
    const int lane   = t & 31;
    const int wid    = t >> 5;
    const int warp_m = wid & 1;
    const int warp_n = wid >> 1;
    const int gid    = lane >> 2;
    const int tig    = lane & 3;
    const int n0     = blockIdx.x * RTILE;
    const int b      = n0 >> 10;
    const int hw0    = n0 & 1023;

    const u32 Abase = smem_u32(smr) + OFF_A;
    const u32 Bbase = smem_u32(smr) + OFF_B0;

    {   // prefetch B tile 0
        const char* src = ((const char*)g_cbbf4);
        for (int i = t; i < 2048; i += 256) {
            int r = i >> 5, c = i & 31;
            cpasync16(Bbase + (u32)(r * 528 + c * 16), src + r * 512 + c * 16);
        }
        cpcommit();
    }

    // ---- prologue: A conversion + exact znorm (threads<64); cn (others) ----
    if (t < RTILE) {
        const float* zb = z + (size_t)b * (D * 1024) + hw0 + t;
        float s = 0.0f;
        for (int d0 = 0; d0 < D; d0 += 8) {
            u16 pk[8];
            #pragma unroll
            for (int i = 0; i < 8; ++i) {
                float v = zb[(size_t)(d0 + i) * 1024];
                s = __fadd_rn(s, __fmul_rn(v, v));      // exact sequential ascending d
                __nv_bfloat16 h = __float2bfloat16(-2.0f * v);
                pk[i] = *(u16*)&h;
            }
            *(uint4*)&Asm[t * ASTRIDE + d0] = *(uint4*)pk;
        }
        zn_s[t] = s;
        float cm = ord2f(g_cnmax);
        marg_s[t] = 0.015625f * sqrtf(s * cm) + 3e-4f;
        rmin_s[t] = 0x7F800000;
        cnt_s[t]  = 0;
        if (t == 0) { *nq_p = 0; *ovf_p = 0; }
    } else {
        for (int i = t - RTILE; i < Kc; i += 256 - RTILE) cn_s[i] = g_cnorm[i];
    }

    float rm[4] = {3.4e38f, 3.4e38f, 3.4e38f, 3.4e38f};
    int   rowv[4];
    #pragma unroll
    for (int r4 = 0; r4 < 4; ++r4)
        rowv[r4] = warp_m * 32 + (r4 >> 1) * 16 + (r4 & 1) * 8 + gid;

    const int ar = warp_m * 32 + (lane & 15);
    const int ak = (lane >> 4) << 3;
    const int bc = warp_n * 16 + ((lane >> 4) & 1) * 8 + (lane & 7);
    const int bk = ((lane >> 3) & 1) * 8;

    for (int nt = 0; nt < NTILES; ++nt) {
        cpwait0();
        __syncthreads();
        if (nt < NTILES - 1) {
            const char* src = ((const char*)g_cbbf4) + (size_t)(nt + 1) * BTILE * 512;
            u32 dstb = Bbase + (u32)(((nt + 1) & 1) * TILE_Bb);
            for (int i = t; i < 2048; i += 256) {
                int r = i >> 5, c = i & 31;
                cpasync16(dstb + (u32)(r * 528 + c * 16), src + r * 512 + c * 16);
            }
            cpcommit();
        }
        const u32 Bb = Bbase + (u32)((nt & 1) * TILE_Bb);

        float acc[2][2][4];
        #pragma unroll
        for (int mt = 0; mt < 2; ++mt)
            #pragma unroll
            for (int j = 0; j < 2; ++j)
                #pragma unroll
                for (int c = 0; c < 4; ++c) acc[mt][j][c] = 0.0f;

        u32 af[2][2][4], bq[2][4];
        #pragma unroll
        for (int mt = 0; mt < 2; ++mt)
            ldsm4(af[0][mt], Abase + (u32)(((ar + mt * 16) * ASTRIDE + ak) * 2));
        ldsm4(bq[0], Bb + (u32)((bc * ASTRIDE + bk) * 2));
        #pragma unroll
        for (int kk = 0; kk < 16; ++kk) {
            const int cur = kk & 1, nxt = cur ^ 1;
            if (kk < 15) {
                int ko = (kk + 1) * 16;
                #pragma unroll
                for (int mt = 0; mt < 2; ++mt)
                    ldsm4(af[nxt][mt], Abase + (u32)(((ar + mt * 16) * ASTRIDE + ko + ak) * 2));
                ldsm4(bq[nxt], Bb + (u32)((bc * ASTRIDE + ko + bk) * 2));
            }
            #pragma unroll
            for (int mt = 0; mt < 2; ++mt) {
                mma16816(acc[mt][0], af[cur][mt], bq[cur][0], bq[cur][1]);
                mma16816(acc[mt][1], af[cur][mt], bq[cur][2], bq[cur][3]);
            }
        }

        // ---- barrier-free filter epilogue ----
        float cnv[4];
        #pragma unroll
        for (int j = 0; j < 2; ++j) {
            int cd = nt * BTILE + warp_n * 16 + j * 8 + tig * 2;
            cnv[j * 2]     = cn_s[cd];
            cnv[j * 2 + 1] = cn_s[cd + 1];
        }
        #pragma unroll
        for (int mt = 0; mt < 2; ++mt)
            #pragma unroll
            for (int j = 0; j < 2; ++j)
                #pragma unroll
                for (int c = 0; c < 2; ++c) {
                    float g0 = cnv[j * 2 + c] + acc[mt][j][c];
                    float g1 = cnv[j * 2 + c] + acc[mt][j][2 + c];
                    rm[mt * 2]     = fminf(rm[mt * 2], g0);
                    rm[mt * 2 + 1] = fminf(rm[mt * 2 + 1], g1);
                }
        #pragma unroll
        for (int r4 = 0; r4 < 4; ++r4) {
            rm[r4] = fminf(rm[r4], __shfl_xor_sync(0xFFFFFFFF, rm[r4], 1));
            rm[r4] = fminf(rm[r4], __shfl_xor_sync(0xFFFFFFFF, rm[r4], 2));
        }
        if (tig == 0) {
            #pragma unroll
            for (int r4 = 0; r4 < 4; ++r4)
                atomicMin(&rmin_s[rowv[r4]], f2ord(rm[r4]));
        }
        float thr[4];
        #pragma unroll
        for (int r4 = 0; r4 < 4; ++r4)
            thr[r4] = fminf(rm[r4], ord2f(rmin_s[rowv[r4]])) + marg_s[rowv[r4]];

        #pragma unroll
        for (int mt = 0; mt < 2; ++mt)
            #pragma unroll
            for (int j = 0; j < 2; ++j)
                #pragma unroll
                for (int c = 0; c < 2; ++c) {
                    int code = nt * BTILE + warp_n * 16 + j * 8 + tig * 2 + c;
                    float g0 = cnv[j * 2 + c] + acc[mt][j][c];
                    float g1 = cnv[j * 2 + c] + acc[mt][j][2 + c];
                    if (g0 <= thr[mt * 2]) {
                        int row = warp_m * 32 + mt * 16 + gid;
                        int sl = atomicAdd(&cnt_s[row], 1);
                        if (sl < CAP) cand_s[row * CAP + sl] = (u16)code;
                    }
                    if (g1 <= thr[mt * 2 + 1]) {
                        int row = warp_m * 32 + mt * 16 + 8 + gid;
                        int sl = atomicAdd(&cnt_s[row], 1);
                        if (sl < CAP) cand_s[row * CAP + sl] = (u16)code;
                    }
                }
    }
    __syncthreads();   // mainloop fully done: A, B0, B1 now reusable

    // ---- stage fp32 z into z_s (overlays A+B0; coalesced, L2-warm) ----
    {
        const float* zb2 = z + (size_t)b * (D * 1024) + hw0;
        for (int i = t; i < RTILE * D; i += 256) {
            int d = i >> 6, j = i & 63;
            z_s[j * 257 + d] = zb2[(size_t)d * 1024 + j];
        }
    }
    __syncthreads();

    // ---- build task queue (one thread per row; tasks overlay B1) ----
    if (t < RTILE) {
        int cnt = cnt_s[t];
        if (cnt == 1) {
            best_s[t] = skey(-3.4e38f, cand_s[t * CAP] & 1023);
        } else if (cnt <= CAP) {
            best_s[t] = ~0ull;
            int base = atomicAdd(nq_p, cnt);
            for (int i = 0; i < cnt; ++i)
                tasks[base + i] = ((u32)t << 16) | (cand_s[t * CAP + i] & 1023);
        } else {
            best_s[t] = ~0ull;
            atomicExch(ovf_p, 1);
        }
    }
    __syncthreads();

    // ---- exact verify: one bit-exact dot chain per task, concurrent ----
    {
        int total = *nq_p;
        for (int i = t; i < total; i += 256) {
            u32 tk   = tasks[i];
            int r    = tk >> 16;
            int code = tk & 0xFFFF;
            const float4* cr4 = (const float4*)(cb + (size_t)code * D);
            const float* zr = z_s + r * 257;
            float dot = 0.0f;
            #pragma unroll 4
            for (int d4 = 0; d4 < D / 4; ++d4) {
                float4 c4 = cr4[d4];
                int d = d4 * 4;
                dot = fmaf(zr[d    ], c4.x, dot);   // sequential ascending d
                dot = fmaf(zr[d + 1], c4.y, dot);
                dot = fmaf(zr[d + 2], c4.z, dot);
                dot = fmaf(zr[d + 3], c4.w, dot);
            }
            float t1 = __fadd_rn(zn_s[r], cn_s[code]);
            float sc = __fadd_rn(t1, __fmul_rn(-2.0f, dot));
            atomicMin(&best_s[r], skey(sc, code));
        }
    }
    __syncthreads();

    // ---- overflow fallback (~never): block-wide exact scan per bad row ----
    if (*ovf_p) {
        for (int r = 0; r < RTILE; ++r) {
            if (cnt_s[r] <= CAP) continue;
            const float* zr = z_s + r * 257;
            float zn = zn_s[r];
            for (int code = t; code < Kc; code += 256) {
                const float4* cr4 = (const float4*)(cb + (size_t)code * D);
                float dot = 0.0f;
                #pragma unroll 4
                for (int d4 = 0; d4 < D / 4; ++d4) {
                    float4 c4 = cr4[d4];
                    int d = d4 * 4;
                    dot = fmaf(zr[d    ], c4.x, dot);
                    dot = fmaf(zr[d + 1], c4.y, dot);
                    dot = fmaf(zr[d + 2], c4.z, dot);
                    dot = fmaf(zr[d + 3], c4.w, dot);
                }
                float t1 = __fadd_rn(zn, cn_s[code]);
                float sc = __fadd_rn(t1, __fmul_rn(-2.0f, dot));
                atomicMin(&best_s[r], skey(sc, code));
            }
        }
        __syncthreads();
    }

    // ---- winners -> idx output ----
    if (t < RTILE)
        out[Z_ELEMS + n0 + t] = (float)(int)(best_s[t] & 1023u);
    __syncthreads();

    // ---- STE + loss, two 32-row halves (q_s overlays B1) ----
    float* ob = out + (size_t)b * (D * 1024) + hw0;
    float ls = 0.0f;
    #pragma unroll
    for (int h = 0; h < 2; ++h) {
        for (int i = t; i < 32 * D; i += 256) {
            int j = i >> 8, d = i & 255;
            int win = (int)(best_s[h * 32 + j] & 1023u);
            q_s[j * 257 + d] = cb[(size_t)win * D + d];
        }
        __syncthreads();
        #pragma unroll
        for (int it = 0; it < 8; ++it) {
            int idx = t + it * 256;
            int j4  = (idx & 7) * 4;
            int d   = idx >> 3;
            float4 zv, qv, ov;
            zv.x = z_s[(h * 32 + j4    ) * 257 + d];
            zv.y = z_s[(h * 32 + j4 + 1) * 257 + d];
            zv.z = z_s[(h * 32 + j4 + 2) * 257 + d];
            zv.w = z_s[(h * 32 + j4 + 3) * 257 + d];
            qv.x = q_s[(j4    ) * 257 + d];
            qv.y = q_s[(j4 + 1) * 257 + d];
            qv.z = q_s[(j4 + 2) * 257 + d];
            qv.w = q_s[(j4 + 3) * 257 + d];
            float dx = __fadd_rn(qv.x, -zv.x); ov.x = __fadd_rn(zv.x, dx);
            float dy = __fadd_rn(qv.y, -zv.y); ov.y = __fadd_rn(zv.y, dy);
            float dz = __fadd_rn(qv.z, -zv.z); ov.z = __fadd_rn(zv.z, dz);
            float dw = __fadd_rn(qv.w, -zv.w); ov.w = __fadd_rn(zv.w, dw);
            *(float4*)&ob[(size_t)d * 1024 + h * 32 + j4] = ov;
            ls += dx * dx + dy * dy + dz * dz + dw * dw;
        }
        __syncthreads();   // before q_s overwrite (h=0) / rs overlay (h=1)
    }

    rs[t] = ls;
    __syncthreads();
    #pragma unroll
    for (int s = 128; s > 0; s >>= 1) {
        if (t < s) rs[t] += rs[t + s];
        __syncthreads();
    }
    if (t == 0) {
        atomicAdd(&g_loss, rs[0]);
        __threadfence();
        unsigned tick = atomicAdd(&g_done, 1u);
        if (tick == (NROWS / RTILE) - 1) {
            out[Z_ELEMS + NROWS] = 1.25f * g_loss / (float)Z_ELEMS;
            g_loss = 0.0f;
            g_done = 0u;
        }
    }
}

// ---------------------------------------------------------------------------
extern "C" void kernel_launch(void* const* d_in, const int* in_sizes, int n_in,
                              void* d_out, int out_size) {
    const float* z  = (const float*)d_in[0];
    const float* cb = (const float*)d_in[1];
    float* out = (float*)d_out;

    cudaFuncSetAttribute(fused_kernel,
                         cudaFuncAttributeMaxDynamicSharedMemorySize, SMEM_TOT);

    prep_kernel<<<128, 128>>>(cb);
    fused_kernel<<<NROWS / RTILE, 256, SMEM_TOT>>>(z, cb, out);
}